// round 13
// baseline (speedup 1.0000x reference)
#include <cuda_runtime.h>
#include <cuda_fp16.h>
#include <math_constants.h>
#include <cstdint>

#define LSEQ 2048
#define DDIM 768
#define KF   16
#define KU   3
#define NFFT 4096
#define RSPEC (2*KF*DDIM)            // 24576
#define RTOT  (RSPEC + KU*DDIM)      // 26880
#define TWO_PI 6.283185307179586476925f

// ---------------- device scratch ----------------
__device__ float  g_xT[DDIM*LSEQ];
__device__ float2 g_Xf[DDIM*NFFT];             // digit-reversed spectra of x
__device__ float2 g_Vf[KF*NFFT];               // digit-reversed spectra of phi, pre-scaled 1/N
__device__ __half g_U[(size_t)RTOT*LSEQ];      // GEMM A in K-major (r,t)
__device__ __half g_B[(size_t)DDIM*RTOT];      // GEMM B (o,r)
__device__ float  g_part[3*(size_t)LSEQ*DDIM]; // split-K partials

// 8th-roots LUT (cos, sin of 2*pi*j/8)
__constant__ float c_r8c[8] = { 1.0f,  0.70710678118654752f, 0.0f, -0.70710678118654752f,
                               -1.0f, -0.70710678118654752f, 0.0f,  0.70710678118654752f };
__constant__ float c_r8s[8] = { 0.0f,  0.70710678118654752f, 1.0f,  0.70710678118654752f,
                                0.0f, -0.70710678118654752f, -1.0f, -0.70710678118654752f };

// ---------------- complex helpers ----------------
__device__ __forceinline__ float2 cmul(float2 a, float2 b) {
    return make_float2(a.x*b.x - a.y*b.y, a.x*b.y + a.y*b.x);
}
__device__ __forceinline__ float2 cadd(float2 a, float2 b){ return make_float2(a.x+b.x, a.y+b.y); }
__device__ __forceinline__ float2 csub(float2 a, float2 b){ return make_float2(a.x-b.x, a.y-b.y); }
template<int S> __device__ __forceinline__ float2 muli(float2 a) {
    return (S > 0) ? make_float2(-a.y, a.x) : make_float2(a.y, -a.x);
}
__device__ __forceinline__ float2 cpow8(float2 a) {      // a^8 via 3 squarings
    float2 b = cmul(a, a);
    b = cmul(b, b);
    return cmul(b, b);
}
// exp(-S*2*pi*i*j/8): stage-base correction factor
template<int S> __device__ __forceinline__ float2 corr8(int j) {
    return make_float2(c_r8c[j], (S > 0) ? -c_r8s[j] : c_r8s[j]);
}
__device__ __forceinline__ uint32_t s2u(const void* p) {
    uint32_t a;
    asm("{ .reg .u64 t; cvta.to.shared.u64 t, %1; cvt.u32.u64 %0, t; }" : "=r"(a) : "l"(p));
    return a;
}
__device__ __forceinline__ void st_cs_u16(__half* p, __half v) {
    asm volatile("st.global.cs.u16 [%0], %1;" :: "l"(p), "h"(__half_as_ushort(v)));
}

template<int S>
__device__ __forceinline__ void dft8(const float2 v[8], float2 o[8]) {
    const float h = 0.70710678118654752440f;
    float2 e0 = cadd(v[0], v[4]), e1 = csub(v[0], v[4]);
    float2 e2 = cadd(v[2], v[6]), e3 = csub(v[2], v[6]);
    float2 A0 = cadd(e0, e2), A2 = csub(e0, e2);
    float2 ie3 = muli<S>(e3);
    float2 A1 = cadd(e1, ie3), A3 = csub(e1, ie3);
    float2 q0 = cadd(v[1], v[5]), q1 = csub(v[1], v[5]);
    float2 q2 = cadd(v[3], v[7]), q3 = csub(v[3], v[7]);
    float2 B0 = cadd(q0, q2), B2 = csub(q0, q2);
    float2 iq3 = muli<S>(q3);
    float2 B1 = cadd(q1, iq3), B3 = csub(q1, iq3);
    B1 = make_float2(h*(B1.x - S*B1.y), h*(S*B1.x + B1.y));
    B2 = muli<S>(B2);
    B3 = make_float2(h*(-B3.x - S*B3.y), h*(S*B3.x - B3.y));
    o[0] = cadd(A0, B0); o[4] = csub(A0, B0);
    o[1] = cadd(A1, B1); o[5] = csub(A1, B1);
    o[2] = cadd(A2, B2); o[6] = csub(A2, B2);
    o[3] = cadd(A3, B3); o[7] = csub(A3, B3);
}

// build w[0..7] from w1 (no MUFU)
__device__ __forceinline__ void twchain_w1(float2 w1, float2 w[8]) {
    w[0] = make_float2(1.0f, 0.0f);
    w[1] = w1;
    #pragma unroll
    for (int m = 2; m < 8; m++) w[m] = cmul(w[m-1], w1);
}

#define FFT_SM 4608   // phys(p) = p + (p>>3)

// Forward radix-8 DIF. ONE sincosf per thread; stage bases derived by powering.
__device__ __forceinline__ void fft8_fwd(float2* sm, int t, float2 v[8], float2 o[8]) {
    float2 w[8];
    float sn, cs; __sincosf(-TWO_PI * (float)t / 4096.0f, &sn, &cs);
    const float2 b4096 = make_float2(cs, sn);        // exp(-2pi i t/4096)
    const float2 b512  = cpow8(b4096);               // exp(-2pi i t/512)
    const float2 b64   = cpow8(b512);                // exp(-2pi i t/64)
    // S0: twiddle base w4096^t
    dft8<-1>(v, o);
    twchain_w1(b4096, w);
    int b0 = t + (t >> 3);
    sm[b0] = o[0];
    #pragma unroll
    for (int m = 1; m < 8; m++) sm[b0 + 576*m] = cmul(o[m], w[m]);
    __syncthreads();
    // S1: base w512^n1 = b512 * corr(t>>6)
    int blk = t >> 6, n1 = t & 63;
    int b1 = 576*blk + n1 + (n1 >> 3);
    #pragma unroll
    for (int j = 0; j < 8; j++) v[j] = sm[b1 + 72*j];
    dft8<-1>(v, o);
    twchain_w1(cmul(b512, corr8<-1>(blk)), w);
    sm[b1] = o[0];
    #pragma unroll
    for (int m = 1; m < 8; m++) sm[b1 + 72*m] = cmul(o[m], w[m]);
    __syncthreads();
    // S2: base w64^n2 = b64 * corr((t>>3)&7)
    int sb = t >> 3, n2 = t & 7;
    int b2 = 72*sb + n2;
    #pragma unroll
    for (int j = 0; j < 8; j++) v[j] = sm[b2 + 9*j];
    dft8<-1>(v, o);
    twchain_w1(cmul(b64, corr8<-1>(sb & 7)), w);
    sm[b2] = o[0];
    #pragma unroll
    for (int m = 1; m < 8; m++) sm[b2 + 9*m] = cmul(o[m], w[m]);
    __syncthreads();
    // S3: stride 1, no twiddle
    int b3 = 9*t;
    #pragma unroll
    for (int j = 0; j < 8; j++) v[j] = sm[b3 + j];
    dft8<-1>(v, o);
}

// Inverse radix-8 DIT. ONE sincosf per thread.
__device__ __forceinline__ void fft8_inv(float2* sm, int t, float2 v[8], float2 o[8]) {
    float2 w[8];
    float sn, cs; __sincosf(TWO_PI * (float)t / 4096.0f, &sn, &cs);
    const float2 b4096 = make_float2(cs, sn);        // exp(+2pi i t/4096)
    const float2 b512  = cpow8(b4096);
    const float2 b64   = cpow8(b512);
    // I0: undo S3
    dft8<1>(v, o);
    int b3 = 9*t;
    #pragma unroll
    for (int m = 0; m < 8; m++) sm[b3 + m] = o[m];
    __syncthreads();
    // I1: undo S2; base w64^n2 = b64 * corr((t>>3)&7)
    int sb = t >> 3, n2 = t & 7;
    int b2 = 72*sb + n2;
    twchain_w1(cmul(b64, corr8<1>(sb & 7)), w);
    #pragma unroll
    for (int m = 0; m < 8; m++) v[m] = cmul(sm[b2 + 9*m], w[m]);
    dft8<1>(v, o);
    #pragma unroll
    for (int m = 0; m < 8; m++) sm[b2 + 9*m] = o[m];
    __syncthreads();
    // I2: undo S1; base w512^n1 = b512 * corr(t>>6)
    int blk = t >> 6, n1 = t & 63;
    int b1 = 576*blk + n1 + (n1 >> 3);
    twchain_w1(cmul(b512, corr8<1>(blk)), w);
    #pragma unroll
    for (int m = 0; m < 8; m++) v[m] = cmul(sm[b1 + 72*m], w[m]);
    dft8<1>(v, o);
    #pragma unroll
    for (int m = 0; m < 8; m++) sm[b1 + 72*m] = o[m];
    __syncthreads();
    // I3: undo S0; base w4096^t
    int b0 = t + (t >> 3);
    twchain_w1(b4096, w);
    #pragma unroll
    for (int m = 0; m < 8; m++) v[m] = cmul(sm[b0 + 576*m], w[m]);
    dft8<1>(v, o);
}

// ---------------- kernels ----------------

__global__ void transpose_kernel(const float* __restrict__ x) {
    __shared__ float tile[32][33];
    int t0 = blockIdx.x * 32;
    int d0 = blockIdx.y * 32;
    int tx = threadIdx.x, ty = threadIdx.y;
    #pragma unroll
    for (int s = 0; s < 32; s += 8)
        tile[ty + s][tx] = x[(t0 + ty + s) * DDIM + d0 + tx];
    __syncthreads();
    #pragma unroll
    for (int s = 0; s < 32; s += 8)
        g_xT[(size_t)(d0 + ty + s) * LSEQ + t0 + tx] = tile[tx][ty + s];
}

__global__ void __launch_bounds__(512) fft_x_kernel() {
    __shared__ float2 sm[FFT_SM];
    int d = blockIdx.x, t = threadIdx.x;
    float2 v[8], o[8];
    #pragma unroll
    for (int j = 0; j < 4; j++)
        v[j] = make_float2(g_xT[(size_t)d * LSEQ + t + 512*j], 0.0f);
    #pragma unroll
    for (int j = 4; j < 8; j++) v[j] = make_float2(0.0f, 0.0f);
    fft8_fwd(sm, t, v, o);
    float2* dst = g_Xf + (size_t)d * NFFT + t*8;
    #pragma unroll
    for (int m = 0; m < 8; m++) dst[m] = o[m];
}

__global__ void __launch_bounds__(512) fft_phi_kernel(const float* __restrict__ phi) {
    __shared__ float2 sm[FFT_SM];
    int k = blockIdx.x, t = threadIdx.x;
    float2 v[8], o[8];
    #pragma unroll
    for (int j = 0; j < 4; j++)
        v[j] = make_float2(phi[(t + 512*j) * KF + k], 0.0f);
    #pragma unroll
    for (int j = 4; j < 8; j++) v[j] = make_float2(0.0f, 0.0f);
    fft8_fwd(sm, t, v, o);
    const float sc = 1.0f / (float)NFFT;
    float2* dst = g_Vf + (size_t)k * NFFT + t*8;
    #pragma unroll
    for (int m = 0; m < 8; m++) dst[m] = make_float2(o[m].x * sc, o[m].y * sc);
}

// b = d*KF + k: the 16 blocks sharing X(d) run concurrently -> L2-hot X.
__global__ void __launch_bounds__(512) conv_ifft_kernel() {
    __shared__ float2 sm[FFT_SM];
    int b = blockIdx.x;
    int d = b >> 4;
    int k = b & 15;
    int t = threadIdx.x;
    const float4* Xp4 = (const float4*)(g_Xf + (size_t)d * NFFT + t*8);
    const float4* Vp4 = (const float4*)(g_Vf + (size_t)k * NFFT + t*8);
    float2 X[8], V[8], v[8], o[8];
    #pragma unroll
    for (int m = 0; m < 4; m++) {
        float4 xv = Xp4[m];
        X[2*m]   = make_float2(xv.x, xv.y);
        X[2*m+1] = make_float2(xv.z, xv.w);
        float4 vv = Vp4[m];
        V[2*m]   = make_float2(vv.x, vv.y);
        V[2*m+1] = make_float2(vv.z, vv.w);
    }
    #pragma unroll
    for (int c = 0; c < 8; c++) {
        float2 Xs = X[c ^ 4];
        float2 comb = make_float2(X[c].x - Xs.y, X[c].y + Xs.x);  // X + i*Xs
        v[c] = cmul(V[c], comb);
    }
    fft8_inv(sm, t, v, o);
    const size_t rowp = (size_t)(k*DDIM + d);
    const size_t rowm = (size_t)(KF*DDIM + k*DDIM + d);
    const float sg = (t & 1) ? -1.0f : 1.0f;
    #pragma unroll
    for (int j = 0; j < 4; j++) {
        int time = t + 512*j;
        st_cs_u16(g_U + rowp * LSEQ + time, __float2half_rn(o[j].x));
        st_cs_u16(g_U + rowm * LSEQ + time, __float2half_rn(o[j].y * sg));
    }
}

// AR rows: g_U[RSPEC + i*DDIM + d][t] = x[t-i][d]
__global__ void arfill_kernel() {
    int idx = blockIdx.x * blockDim.x + threadIdx.x;
    if (idx >= KU * DDIM * (LSEQ/8)) return;
    int tv  = idx & 255;
    int rem = idx >> 8;
    int d   = rem % DDIM;
    int i   = rem / DDIM;
    int t   = tv * 8;
    const float* src = g_xT + (size_t)d * LSEQ;
    __align__(16) __half h[8];
    #pragma unroll
    for (int e = 0; e < 8; e++) {
        int tt = t + e;
        h[e] = __float2half_rn((tt >= i) ? src[tt - i] : 0.0f);
    }
    *(uint4*)(g_U + (size_t)(RSPEC + i*DDIM + d) * LSEQ + t) = *(const uint4*)h;
}

__global__ void mcatT_kernel(const float* __restrict__ Mp,
                             const float* __restrict__ Mm,
                             const float* __restrict__ Mu,
                             const float* __restrict__ sigma) {
    __shared__ float tile[32][33];
    int r0 = blockIdx.x * 32;
    int o0 = blockIdx.y * 32;
    int tx = threadIdx.x, ty = threadIdx.y;
    #pragma unroll
    for (int s = 0; s < 32; s += 8) {
        int r = r0 + ty + s;
        int o = o0 + tx;
        float v;
        if (r < KF*DDIM) {
            v = Mp[(size_t)r * DDIM + o] * sqrtf(sqrtf(sigma[r / DDIM]));
        } else if (r < RSPEC) {
            int rr = r - KF*DDIM;
            v = Mm[(size_t)rr * DDIM + o] * sqrtf(sqrtf(sigma[rr / DDIM]));
        } else {
            v = Mu[(size_t)(r - RSPEC) * DDIM + o];
        }
        tile[ty + s][tx] = v;
    }
    __syncthreads();
    #pragma unroll
    for (int s = 0; s < 32; s += 8)
        g_B[(size_t)(o0 + ty + s) * RTOT + r0 + tx] = __float2half_rn(tile[tx][ty + s]);
}

// ---------------- fp16 mma.sync GEMM, split-K=3, 3-stage pipeline ----------------
#define BM 128
#define BN 128
#define BK 64
#define KSPLIT 3
#define KLEN (RTOT/KSPLIT)      // 8960
#define NKI (KLEN/BK)           // 140
#define ASTRB 272
#define BSTRB 144
#define ATILEB (BK*ASTRB)       // 17408
#define BTILEB (BN*BSTRB)       // 18432
#define STAGEB (ATILEB + BTILEB)// 35840
#define NSTAGE 3

__device__ __forceinline__ void cp16(uint32_t dst, const void* src) {
    asm volatile("cp.async.cg.shared.global [%0], [%1], 16;" :: "r"(dst), "l"(src));
}
#define LDSM4(R, addr) \
    asm volatile("ldmatrix.sync.aligned.m8n8.x4.shared.b16 {%0,%1,%2,%3}, [%4];" \
        : "=r"((R)[0]), "=r"((R)[1]), "=r"((R)[2]), "=r"((R)[3]) : "r"(addr))
#define LDSM4T(R, addr) \
    asm volatile("ldmatrix.sync.aligned.m8n8.x4.trans.shared.b16 {%0,%1,%2,%3}, [%4];" \
        : "=r"((R)[0]), "=r"((R)[1]), "=r"((R)[2]), "=r"((R)[3]) : "r"(addr))
#define MMA16816(C, A, B) \
    asm volatile("mma.sync.aligned.m16n8k16.row.col.f32.f16.f16.f32 " \
        "{%0,%1,%2,%3}, {%4,%5,%6,%7}, {%8,%9}, {%0,%1,%2,%3};" \
        : "+f"((C)[0]), "+f"((C)[1]), "+f"((C)[2]), "+f"((C)[3]) \
        : "r"((A)[0]), "r"((A)[1]), "r"((A)[2]), "r"((A)[3]), "r"((B)[0]), "r"((B)[1]))

__global__ void __launch_bounds__(256, 2) gemm_kernel() {
    extern __shared__ __align__(16) char dsm[];
    const int tid  = threadIdx.x;
    const int lane = tid & 31;
    const int wid  = tid >> 5;
    const int wm   = wid >> 2;
    const int wn   = wid & 3;
    const int t0   = blockIdx.x * BM;
    const int o0   = blockIdx.y * BN;
    const int ks   = blockIdx.z;
    const size_t koff = (size_t)ks * KLEN;
    const uint32_t sbase = s2u(dsm);

    const __half* pA[4]; uint32_t dA[4];
    const __half* pB[4]; uint32_t dB[4];
    #pragma unroll
    for (int q = 0; q < 4; q++) {
        int ida = tid + q*256;
        int kr = ida >> 4, cc = ida & 15;
        pA[q] = g_U + (koff + kr) * LSEQ + t0 + cc*8;
        dA[q] = (uint32_t)(kr*ASTRB + cc*16);
        int idb = tid + q*256;
        int orow = idb >> 3, bc = idb & 7;
        pB[q] = g_B + (size_t)(o0 + orow) * RTOT + koff + bc*8;
        dB[q] = (uint32_t)(ATILEB + orow*BSTRB + bc*16);
    }

    const int akr = (lane & 7) + ((lane >> 4) << 3);
    const int amc = ((lane >> 3) & 1) * 8;
    const int grp = lane >> 3;
    const int rB = ((grp >> 1) << 3) + (lane & 7);
    const int cB = grp & 1;

    float acc[4][4][4];
    #pragma unroll
    for (int mi = 0; mi < 4; mi++)
        #pragma unroll
        for (int ni = 0; ni < 4; ni++)
            #pragma unroll
            for (int e = 0; e < 4; e++) acc[mi][ni][e] = 0.0f;

    #pragma unroll
    for (int st = 0; st < 2; st++) {
        uint32_t s = sbase + st*STAGEB;
        size_t offA = (size_t)st * BK * LSEQ;
        size_t offB = (size_t)st * BK;
        #pragma unroll
        for (int q = 0; q < 4; q++) {
            cp16(s + dA[q], pA[q] + offA);
            cp16(s + dB[q], pB[q] + offB);
        }
        asm volatile("cp.async.commit_group;");
    }

    int buf = 0;
    #pragma unroll 1
    for (int c = 0; c < NKI; c++) {
        if (c + 2 < NKI) {
            int nb = buf + 2; if (nb >= NSTAGE) nb -= NSTAGE;
            uint32_t s = sbase + nb*STAGEB;
            size_t offA = (size_t)(c + 2) * BK * LSEQ;
            size_t offB = (size_t)(c + 2) * BK;
            #pragma unroll
            for (int q = 0; q < 4; q++) {
                cp16(s + dA[q], pA[q] + offA);
                cp16(s + dB[q], pB[q] + offB);
            }
            asm volatile("cp.async.commit_group;");
            asm volatile("cp.async.wait_group %0;" :: "n"(2));
        } else if (c + 1 < NKI) {
            asm volatile("cp.async.wait_group %0;" :: "n"(1));
        } else {
            asm volatile("cp.async.wait_group %0;" :: "n"(0));
        }
        __syncthreads();

        const uint32_t sA = sbase + buf*STAGEB;
        const uint32_t sB = sA + ATILEB;
        #pragma unroll
        for (int j = 0; j < 4; j++) {
            uint32_t a[4][4];
            #pragma unroll
            for (int mi = 0; mi < 4; mi++) {
                uint32_t addr = sA + (uint32_t)((j*16 + akr)*ASTRB + (wm*64 + mi*16 + amc)*2);
                LDSM4T(a[mi], addr);
            }
            uint32_t b[4][2];
            #pragma unroll
            for (int half = 0; half < 2; half++) {
                uint32_t addr = sB + (uint32_t)((wn*32 + half*16 + rB)*BSTRB + (j*16 + cB*8)*2);
                uint32_t r4[4]; LDSM4(r4, addr);
                b[2*half][0]   = r4[0]; b[2*half][1]   = r4[1];
                b[2*half+1][0] = r4[2]; b[2*half+1][1] = r4[3];
            }
            #pragma unroll
            for (int mi = 0; mi < 4; mi++)
                #pragma unroll
                for (int ni = 0; ni < 4; ni++)
                    MMA16816(acc[mi][ni], a[mi], b[ni]);
        }
        __syncthreads();
        buf++; if (buf >= NSTAGE) buf = 0;
    }

    float* pp = g_part + (size_t)ks * LSEQ * DDIM;
    const int row  = lane >> 2;
    const int col2 = (lane & 3) * 2;
    #pragma unroll
    for (int mi = 0; mi < 4; mi++) {
        #pragma unroll
        for (int ni = 0; ni < 4; ni++) {
            int t = t0 + wm*64 + mi*16 + row;
            int o = o0 + wn*32 + ni*8 + col2;
            float* p0 = pp + (size_t)t * DDIM + o;
            float* p1 = pp + (size_t)(t + 8) * DDIM + o;
            p0[0] = acc[mi][ni][0]; p0[1] = acc[mi][ni][1];
            p1[0] = acc[mi][ni][2]; p1[1] = acc[mi][ni][3];
        }
    }
}

__global__ void reduce_kernel(float* __restrict__ out) {
    int i = blockIdx.x * blockDim.x + threadIdx.x;
    const float4* p0 = (const float4*)g_part;
    const float4* p1 = (const float4*)(g_part + (size_t)LSEQ*DDIM);
    const float4* p2 = (const float4*)(g_part + 2*(size_t)LSEQ*DDIM);
    float4 a = p0[i], b = p1[i], c = p2[i];
    ((float4*)out)[i] = make_float4(a.x+b.x+c.x, a.y+b.y+c.y, a.z+b.z+c.z, a.w+b.w+c.w);
}

// ---------------- launch ----------------
extern "C" void kernel_launch(void* const* d_in, const int* in_sizes, int n_in,
                              void* d_out, int out_size) {
    const float* x     = (const float*)d_in[0];
    const float* phi   = (const float*)d_in[1];
    const float* sigma = (const float*)d_in[2];
    const float* Mp    = (const float*)d_in[3];
    const float* Mm    = (const float*)d_in[4];
    const float* Mu    = (const float*)d_in[5];
    float* out = (float*)d_out;

    cudaFuncSetAttribute(gemm_kernel, cudaFuncAttributeMaxDynamicSharedMemorySize, NSTAGE*STAGEB);

    transpose_kernel<<<dim3(LSEQ/32, DDIM/32), dim3(32, 8)>>>(x);
    fft_x_kernel<<<DDIM, 512>>>();
    fft_phi_kernel<<<KF, 512>>>(phi);
    conv_ifft_kernel<<<KF*DDIM, 512>>>();
    arfill_kernel<<<(KU*DDIM*(LSEQ/8) + 255)/256, 256>>>();
    mcatT_kernel<<<dim3(RTOT/32, DDIM/32), dim3(32, 8)>>>(Mp, Mm, Mu, sigma);
    gemm_kernel<<<dim3(LSEQ/BM, DDIM/BN, KSPLIT), 256, NSTAGE*STAGEB>>>();
    reduce_kernel<<<(LSEQ*DDIM/4 + 255)/256, 256>>>(out);
}

// round 14
// speedup vs baseline: 1.1016x; 1.1016x over previous
#include <cuda_runtime.h>
#include <cuda_fp16.h>
#include <math_constants.h>
#include <cstdint>

#define LSEQ 2048
#define DDIM 768
#define KF   16
#define KU   3
#define NFFT 4096
#define RSPEC (2*KF*DDIM)            // 24576
#define RTOT  (RSPEC + KU*DDIM)      // 26880
#define TWO_PI 6.283185307179586476925f

// ---------------- device scratch ----------------
__device__ float  g_xT[DDIM*LSEQ];
__device__ float2 g_Xf[DDIM*NFFT];             // digit-reversed spectra of x
__device__ float2 g_Vf[KF*NFFT];               // digit-reversed spectra of phi, pre-scaled 1/N
__device__ __half g_U[(size_t)RTOT*LSEQ];      // GEMM A in K-major (r,t)
__device__ __half g_B[(size_t)DDIM*RTOT];      // GEMM B (o,r)
__device__ float  g_part[3*(size_t)LSEQ*DDIM]; // split-K partials

// ---------------- complex helpers ----------------
__device__ __forceinline__ float2 cmul(float2 a, float2 b) {
    return make_float2(a.x*b.x - a.y*b.y, a.x*b.y + a.y*b.x);
}
__device__ __forceinline__ float2 cadd(float2 a, float2 b){ return make_float2(a.x+b.x, a.y+b.y); }
__device__ __forceinline__ float2 csub(float2 a, float2 b){ return make_float2(a.x-b.x, a.y-b.y); }
template<int S> __device__ __forceinline__ float2 muli(float2 a) {
    return (S > 0) ? make_float2(-a.y, a.x) : make_float2(a.y, -a.x);
}
__device__ __forceinline__ uint32_t s2u(const void* p) {
    uint32_t a;
    asm("{ .reg .u64 t; cvta.to.shared.u64 t, %1; cvt.u32.u64 %0, t; }" : "=r"(a) : "l"(p));
    return a;
}
__device__ __forceinline__ void st_cs_u16(__half* p, __half v) {
    asm volatile("st.global.cs.u16 [%0], %1;" :: "l"(p), "h"(__half_as_ushort(v)));
}

template<int S>
__device__ __forceinline__ void dft8(const float2 v[8], float2 o[8]) {
    const float h = 0.70710678118654752440f;
    float2 e0 = cadd(v[0], v[4]), e1 = csub(v[0], v[4]);
    float2 e2 = cadd(v[2], v[6]), e3 = csub(v[2], v[6]);
    float2 A0 = cadd(e0, e2), A2 = csub(e0, e2);
    float2 ie3 = muli<S>(e3);
    float2 A1 = cadd(e1, ie3), A3 = csub(e1, ie3);
    float2 q0 = cadd(v[1], v[5]), q1 = csub(v[1], v[5]);
    float2 q2 = cadd(v[3], v[7]), q3 = csub(v[3], v[7]);
    float2 B0 = cadd(q0, q2), B2 = csub(q0, q2);
    float2 iq3 = muli<S>(q3);
    float2 B1 = cadd(q1, iq3), B3 = csub(q1, iq3);
    B1 = make_float2(h*(B1.x - S*B1.y), h*(S*B1.x + B1.y));
    B2 = muli<S>(B2);
    B3 = make_float2(h*(-B3.x - S*B3.y), h*(S*B3.x - B3.y));
    o[0] = cadd(A0, B0); o[4] = csub(A0, B0);
    o[1] = cadd(A1, B1); o[5] = csub(A1, B1);
    o[2] = cadd(A2, B2); o[6] = csub(A2, B2);
    o[3] = cadd(A3, B3); o[7] = csub(A3, B3);
}

__device__ __forceinline__ void twchain(float theta, float2 w[8]) {
    float sn, cs; __sincosf(theta, &sn, &cs);
    w[0] = make_float2(1.0f, 0.0f);
    w[1] = make_float2(cs, sn);
    #pragma unroll
    for (int m = 2; m < 8; m++) w[m] = cmul(w[m-1], w[1]);
}

#define FFT_SM 4608   // phys(p) = p + (p>>3)

// fp32 forward radix-8 DIF (used by fft_x / fft_phi; not hot)
__device__ __forceinline__ void fft8_fwd(float2* sm, int t, float2 v[8], float2 o[8]) {
    float2 w[8];
    dft8<-1>(v, o);
    twchain(-TWO_PI * (float)t / 4096.0f, w);
    int b0 = t + (t >> 3);
    sm[b0] = o[0];
    #pragma unroll
    for (int m = 1; m < 8; m++) sm[b0 + 576*m] = cmul(o[m], w[m]);
    __syncthreads();
    int blk = t >> 6, n1 = t & 63;
    int b1 = 576*blk + n1 + (n1 >> 3);
    #pragma unroll
    for (int j = 0; j < 8; j++) v[j] = sm[b1 + 72*j];
    dft8<-1>(v, o);
    twchain(-TWO_PI * (float)n1 / 512.0f, w);
    sm[b1] = o[0];
    #pragma unroll
    for (int m = 1; m < 8; m++) sm[b1 + 72*m] = cmul(o[m], w[m]);
    __syncthreads();
    int sb = t >> 3, n2 = t & 7;
    int b2 = 72*sb + n2;
    #pragma unroll
    for (int j = 0; j < 8; j++) v[j] = sm[b2 + 9*j];
    dft8<-1>(v, o);
    twchain(-TWO_PI * (float)n2 / 64.0f, w);
    sm[b2] = o[0];
    #pragma unroll
    for (int m = 1; m < 8; m++) sm[b2 + 9*m] = cmul(o[m], w[m]);
    __syncthreads();
    int b3 = 9*t;
    #pragma unroll
    for (int j = 0; j < 8; j++) v[j] = sm[b3 + j];
    dft8<-1>(v, o);
}

// Inverse radix-8 DIT with fp16 smem exchanges (compute stays fp32).
__device__ __forceinline__ void fft8_inv_h(__half2* sm, int t, float2 v[8], float2 o[8]) {
    float2 w[8];
    // I0: undo S3
    dft8<1>(v, o);
    int b3 = 9*t;
    #pragma unroll
    for (int m = 0; m < 8; m++) sm[b3 + m] = __float22half2_rn(o[m]);
    __syncthreads();
    // I1: undo S2
    int sb = t >> 3, n2 = t & 7;
    int b2 = 72*sb + n2;
    twchain(TWO_PI * (float)n2 / 64.0f, w);
    #pragma unroll
    for (int m = 0; m < 8; m++) v[m] = cmul(__half22float2(sm[b2 + 9*m]), w[m]);
    dft8<1>(v, o);
    #pragma unroll
    for (int m = 0; m < 8; m++) sm[b2 + 9*m] = __float22half2_rn(o[m]);
    __syncthreads();
    // I2: undo S1
    int blk = t >> 6, n1 = t & 63;
    int b1 = 576*blk + n1 + (n1 >> 3);
    twchain(TWO_PI * (float)n1 / 512.0f, w);
    #pragma unroll
    for (int m = 0; m < 8; m++) v[m] = cmul(__half22float2(sm[b1 + 72*m]), w[m]);
    dft8<1>(v, o);
    #pragma unroll
    for (int m = 0; m < 8; m++) sm[b1 + 72*m] = __float22half2_rn(o[m]);
    __syncthreads();
    // I3: undo S0
    int b0 = t + (t >> 3);
    twchain(TWO_PI * (float)t / 4096.0f, w);
    #pragma unroll
    for (int m = 0; m < 8; m++) v[m] = cmul(__half22float2(sm[b0 + 576*m]), w[m]);
    dft8<1>(v, o);
}

// ---------------- kernels ----------------

__global__ void transpose_kernel(const float* __restrict__ x) {
    __shared__ float tile[32][33];
    int t0 = blockIdx.x * 32;
    int d0 = blockIdx.y * 32;
    int tx = threadIdx.x, ty = threadIdx.y;
    #pragma unroll
    for (int s = 0; s < 32; s += 8)
        tile[ty + s][tx] = x[(t0 + ty + s) * DDIM + d0 + tx];
    __syncthreads();
    #pragma unroll
    for (int s = 0; s < 32; s += 8)
        g_xT[(size_t)(d0 + ty + s) * LSEQ + t0 + tx] = tile[tx][ty + s];
}

__global__ void __launch_bounds__(512) fft_x_kernel() {
    __shared__ float2 sm[FFT_SM];
    int d = blockIdx.x, t = threadIdx.x;
    float2 v[8], o[8];
    #pragma unroll
    for (int j = 0; j < 4; j++)
        v[j] = make_float2(g_xT[(size_t)d * LSEQ + t + 512*j], 0.0f);
    #pragma unroll
    for (int j = 4; j < 8; j++) v[j] = make_float2(0.0f, 0.0f);
    fft8_fwd(sm, t, v, o);
    float2* dst = g_Xf + (size_t)d * NFFT + t*8;
    #pragma unroll
    for (int m = 0; m < 8; m++) dst[m] = o[m];
}

__global__ void __launch_bounds__(512) fft_phi_kernel(const float* __restrict__ phi) {
    __shared__ float2 sm[FFT_SM];
    int k = blockIdx.x, t = threadIdx.x;
    float2 v[8], o[8];
    #pragma unroll
    for (int j = 0; j < 4; j++)
        v[j] = make_float2(phi[(t + 512*j) * KF + k], 0.0f);
    #pragma unroll
    for (int j = 4; j < 8; j++) v[j] = make_float2(0.0f, 0.0f);
    fft8_fwd(sm, t, v, o);
    const float sc = 1.0f / (float)NFFT;
    float2* dst = g_Vf + (size_t)k * NFFT + t*8;
    #pragma unroll
    for (int m = 0; m < 8; m++) dst[m] = make_float2(o[m].x * sc, o[m].y * sc);
}

// b = d*KF + k: 16 blocks sharing X(d) run concurrently -> L2-hot X.
__global__ void __launch_bounds__(512) conv_ifft_kernel() {
    __shared__ __half2 sm[FFT_SM];
    int b = blockIdx.x;
    int d = b >> 4;
    int k = b & 15;
    int t = threadIdx.x;
    const float4* Xp4 = (const float4*)(g_Xf + (size_t)d * NFFT + t*8);
    const float4* Vp4 = (const float4*)(g_Vf + (size_t)k * NFFT + t*8);
    float2 X[8], V[8], v[8], o[8];
    #pragma unroll
    for (int m = 0; m < 4; m++) {
        float4 xv = Xp4[m];
        X[2*m]   = make_float2(xv.x, xv.y);
        X[2*m+1] = make_float2(xv.z, xv.w);
        float4 vv = Vp4[m];
        V[2*m]   = make_float2(vv.x, vv.y);
        V[2*m+1] = make_float2(vv.z, vv.w);
    }
    #pragma unroll
    for (int c = 0; c < 8; c++) {
        float2 Xs = X[c ^ 4];
        float2 comb = make_float2(X[c].x - Xs.y, X[c].y + Xs.x);  // X + i*Xs
        v[c] = cmul(V[c], comb);
    }
    fft8_inv_h(sm, t, v, o);
    const size_t rowp = (size_t)(k*DDIM + d);
    const size_t rowm = (size_t)(KF*DDIM + k*DDIM + d);
    const float sg = (t & 1) ? -1.0f : 1.0f;
    #pragma unroll
    for (int j = 0; j < 4; j++) {
        int time = t + 512*j;
        st_cs_u16(g_U + rowp * LSEQ + time, __float2half_rn(o[j].x));
        st_cs_u16(g_U + rowm * LSEQ + time, __float2half_rn(o[j].y * sg));
    }
}

// AR rows: g_U[RSPEC + i*DDIM + d][t] = x[t-i][d]
__global__ void arfill_kernel() {
    int idx = blockIdx.x * blockDim.x + threadIdx.x;
    if (idx >= KU * DDIM * (LSEQ/8)) return;
    int tv  = idx & 255;
    int rem = idx >> 8;
    int d   = rem % DDIM;
    int i   = rem / DDIM;
    int t   = tv * 8;
    const float* src = g_xT + (size_t)d * LSEQ;
    __align__(16) __half h[8];
    #pragma unroll
    for (int e = 0; e < 8; e++) {
        int tt = t + e;
        h[e] = __float2half_rn((tt >= i) ? src[tt - i] : 0.0f);
    }
    *(uint4*)(g_U + (size_t)(RSPEC + i*DDIM + d) * LSEQ + t) = *(const uint4*)h;
}

__global__ void mcatT_kernel(const float* __restrict__ Mp,
                             const float* __restrict__ Mm,
                             const float* __restrict__ Mu,
                             const float* __restrict__ sigma) {
    __shared__ float tile[32][33];
    int r0 = blockIdx.x * 32;
    int o0 = blockIdx.y * 32;
    int tx = threadIdx.x, ty = threadIdx.y;
    #pragma unroll
    for (int s = 0; s < 32; s += 8) {
        int r = r0 + ty + s;
        int o = o0 + tx;
        float v;
        if (r < KF*DDIM) {
            v = Mp[(size_t)r * DDIM + o] * sqrtf(sqrtf(sigma[r / DDIM]));
        } else if (r < RSPEC) {
            int rr = r - KF*DDIM;
            v = Mm[(size_t)rr * DDIM + o] * sqrtf(sqrtf(sigma[rr / DDIM]));
        } else {
            v = Mu[(size_t)(r - RSPEC) * DDIM + o];
        }
        tile[ty + s][tx] = v;
    }
    __syncthreads();
    #pragma unroll
    for (int s = 0; s < 32; s += 8)
        g_B[(size_t)(o0 + ty + s) * RTOT + r0 + tx] = __float2half_rn(tile[tx][ty + s]);
}

// ---------------- fp16 mma.sync GEMM, split-K=3, 3-stage single-sync pipeline ----------------
#define BM 128
#define BN 128
#define BK 64
#define KSPLIT 3
#define KLEN (RTOT/KSPLIT)      // 8960
#define NKI (KLEN/BK)           // 140
#define ASTRB 272
#define BSTRB 144
#define ATILEB (BK*ASTRB)       // 17408
#define BTILEB (BN*BSTRB)       // 18432
#define STAGEB (ATILEB + BTILEB)// 35840
#define NSTAGE 3

__device__ __forceinline__ void cp16(uint32_t dst, const void* src) {
    asm volatile("cp.async.cg.shared.global [%0], [%1], 16;" :: "r"(dst), "l"(src));
}
#define LDSM4(R, addr) \
    asm volatile("ldmatrix.sync.aligned.m8n8.x4.shared.b16 {%0,%1,%2,%3}, [%4];" \
        : "=r"((R)[0]), "=r"((R)[1]), "=r"((R)[2]), "=r"((R)[3]) : "r"(addr))
#define LDSM4T(R, addr) \
    asm volatile("ldmatrix.sync.aligned.m8n8.x4.trans.shared.b16 {%0,%1,%2,%3}, [%4];" \
        : "=r"((R)[0]), "=r"((R)[1]), "=r"((R)[2]), "=r"((R)[3]) : "r"(addr))
#define MMA16816(C, A, B) \
    asm volatile("mma.sync.aligned.m16n8k16.row.col.f32.f16.f16.f32 " \
        "{%0,%1,%2,%3}, {%4,%5,%6,%7}, {%8,%9}, {%0,%1,%2,%3};" \
        : "+f"((C)[0]), "+f"((C)[1]), "+f"((C)[2]), "+f"((C)[3]) \
        : "r"((A)[0]), "r"((A)[1]), "r"((A)[2]), "r"((A)[3]), "r"((B)[0]), "r"((B)[1]))

__global__ void __launch_bounds__(256, 2) gemm_kernel() {
    extern __shared__ __align__(16) char dsm[];
    const int tid  = threadIdx.x;
    const int lane = tid & 31;
    const int wid  = tid >> 5;
    const int wm   = wid >> 2;
    const int wn   = wid & 3;
    const int t0   = blockIdx.x * BM;
    const int o0   = blockIdx.y * BN;
    const int ks   = blockIdx.z;
    const size_t koff = (size_t)ks * KLEN;
    const uint32_t sbase = s2u(dsm);

    const __half* pA[4]; uint32_t dA[4];
    const __half* pB[4]; uint32_t dB[4];
    #pragma unroll
    for (int q = 0; q < 4; q++) {
        int ida = tid + q*256;
        int kr = ida >> 4, cc = ida & 15;
        pA[q] = g_U + (koff + kr) * LSEQ + t0 + cc*8;
        dA[q] = (uint32_t)(kr*ASTRB + cc*16);
        int idb = tid + q*256;
        int orow = idb >> 3, bc = idb & 7;
        pB[q] = g_B + (size_t)(o0 + orow) * RTOT + koff + bc*8;
        dB[q] = (uint32_t)(ATILEB + orow*BSTRB + bc*16);
    }

    const int akr = (lane & 7) + ((lane >> 4) << 3);
    const int amc = ((lane >> 3) & 1) * 8;
    const int grp = lane >> 3;
    const int rB = ((grp >> 1) << 3) + (lane & 7);
    const int cB = grp & 1;

    float acc[4][4][4];
    #pragma unroll
    for (int mi = 0; mi < 4; mi++)
        #pragma unroll
        for (int ni = 0; ni < 4; ni++)
            #pragma unroll
            for (int e = 0; e < 4; e++) acc[mi][ni][e] = 0.0f;

    #pragma unroll
    for (int st = 0; st < 2; st++) {
        uint32_t s = sbase + st*STAGEB;
        size_t offA = (size_t)st * BK * LSEQ;
        size_t offB = (size_t)st * BK;
        #pragma unroll
        for (int q = 0; q < 4; q++) {
            cp16(s + dA[q], pA[q] + offA);
            cp16(s + dB[q], pB[q] + offB);
        }
        asm volatile("cp.async.commit_group;");
    }

    int buf = 0;
    #pragma unroll 1
    for (int c = 0; c < NKI; c++) {
        if (c + 1 < NKI) {
            asm volatile("cp.async.wait_group %0;" :: "n"(1));
        } else {
            asm volatile("cp.async.wait_group %0;" :: "n"(0));
        }
        __syncthreads();

        const uint32_t sA = sbase + buf*STAGEB;
        const uint32_t sB = sA + ATILEB;
        #pragma unroll
        for (int j = 0; j < 4; j++) {
            uint32_t a[4][4];
            #pragma unroll
            for (int mi = 0; mi < 4; mi++) {
                uint32_t addr = sA + (uint32_t)((j*16 + akr)*ASTRB + (wm*64 + mi*16 + amc)*2);
                LDSM4T(a[mi], addr);
            }
            uint32_t b[4][2];
            #pragma unroll
            for (int half = 0; half < 2; half++) {
                uint32_t addr = sB + (uint32_t)((wn*32 + half*16 + rB)*BSTRB + (j*16 + cB*8)*2);
                uint32_t r4[4]; LDSM4(r4, addr);
                b[2*half][0]   = r4[0]; b[2*half][1]   = r4[1];
                b[2*half+1][0] = r4[2]; b[2*half+1][1] = r4[3];
            }
            #pragma unroll
            for (int mi = 0; mi < 4; mi++)
                #pragma unroll
                for (int ni = 0; ni < 4; ni++)
                    MMA16816(acc[mi][ni], a[mi], b[ni]);
        }

        // prefetch stage c+2 into slot (buf+2)%3 == slot (c-1)%3; safe: all warps
        // passed the barrier above, so slot (c-1) has no remaining readers, and
        // compute(c) above read slot c only.
        if (c + 2 < NKI) {
            int nb = buf + 2; if (nb >= NSTAGE) nb -= NSTAGE;
            uint32_t s = sbase + nb*STAGEB;
            size_t offA = (size_t)(c + 2) * BK * LSEQ;
            size_t offB = (size_t)(c + 2) * BK;
            #pragma unroll
            for (int q = 0; q < 4; q++) {
                cp16(s + dA[q], pA[q] + offA);
                cp16(s + dB[q], pB[q] + offB);
            }
            asm volatile("cp.async.commit_group;");
        }
        buf++; if (buf >= NSTAGE) buf = 0;
    }

    float* pp = g_part + (size_t)ks * LSEQ * DDIM;
    const int row  = lane >> 2;
    const int col2 = (lane & 3) * 2;
    #pragma unroll
    for (int mi = 0; mi < 4; mi++) {
        #pragma unroll
        for (int ni = 0; ni < 4; ni++) {
            int t = t0 + wm*64 + mi*16 + row;
            int o = o0 + wn*32 + ni*8 + col2;
            float* p0 = pp + (size_t)t * DDIM + o;
            float* p1 = pp + (size_t)(t + 8) * DDIM + o;
            p0[0] = acc[mi][ni][0]; p0[1] = acc[mi][ni][1];
            p1[0] = acc[mi][ni][2]; p1[1] = acc[mi][ni][3];
        }
    }
}

__global__ void reduce_kernel(float* __restrict__ out) {
    int i = blockIdx.x * blockDim.x + threadIdx.x;
    const float4* p0 = (const float4*)g_part;
    const float4* p1 = (const float4*)(g_part + (size_t)LSEQ*DDIM);
    const float4* p2 = (const float4*)(g_part + 2*(size_t)LSEQ*DDIM);
    float4 a = p0[i], b = p1[i], c = p2[i];
    ((float4*)out)[i] = make_float4(a.x+b.x+c.x, a.y+b.y+c.y, a.z+b.z+c.z, a.w+b.w+c.w);
}

// ---------------- launch ----------------
extern "C" void kernel_launch(void* const* d_in, const int* in_sizes, int n_in,
                              void* d_out, int out_size) {
    const float* x     = (const float*)d_in[0];
    const float* phi   = (const float*)d_in[1];
    const float* sigma = (const float*)d_in[2];
    const float* Mp    = (const float*)d_in[3];
    const float* Mm    = (const float*)d_in[4];
    const float* Mu    = (const float*)d_in[5];
    float* out = (float*)d_out;

    cudaFuncSetAttribute(gemm_kernel, cudaFuncAttributeMaxDynamicSharedMemorySize, NSTAGE*STAGEB);

    transpose_kernel<<<dim3(LSEQ/32, DDIM/32), dim3(32, 8)>>>(x);
    fft_x_kernel<<<DDIM, 512>>>();
    fft_phi_kernel<<<KF, 512>>>(phi);
    conv_ifft_kernel<<<KF*DDIM, 512>>>();
    arfill_kernel<<<(KU*DDIM*(LSEQ/8) + 255)/256, 256>>>();
    mcatT_kernel<<<dim3(RTOT/32, DDIM/32), dim3(32, 8)>>>(Mp, Mm, Mu, sigma);
    gemm_kernel<<<dim3(LSEQ/BM, DDIM/BN, KSPLIT), 256, NSTAGE*STAGEB>>>();
    reduce_kernel<<<(LSEQ*DDIM/4 + 255)/256, 256>>>(out);
}

// round 15
// speedup vs baseline: 1.1251x; 1.0213x over previous
#include <cuda_runtime.h>
#include <cuda_fp16.h>
#include <math_constants.h>
#include <cstdint>

#define LSEQ 2048
#define DDIM 768
#define KF   16
#define KU   3
#define NFFT 4096
#define RSPEC (2*KF*DDIM)            // 24576
#define RTOT  (RSPEC + KU*DDIM)      // 26880
#define TWO_PI 6.283185307179586476925f

// ---------------- device scratch ----------------
__device__ float  g_xT[DDIM*LSEQ];
__device__ float2 g_Xf[DDIM*NFFT];             // digit-reversed spectra of x
__device__ float2 g_Vf[KF*NFFT];               // digit-reversed spectra of phi, pre-scaled 1/N
__device__ __half g_U[(size_t)RTOT*LSEQ];      // GEMM A in K-major (r,t)
__device__ __half g_B[(size_t)DDIM*RTOT];      // GEMM B (o,r)
__device__ float  g_part[3*(size_t)LSEQ*DDIM]; // split-K partials

// ---------------- complex helpers (packed f32x2 adds) ----------------
__device__ __forceinline__ unsigned long long f2u(float2 v) {
    unsigned long long u;
    asm("mov.b64 %0, {%1, %2};" : "=l"(u) : "f"(v.x), "f"(v.y));
    return u;
}
__device__ __forceinline__ float2 u2f(unsigned long long u) {
    float2 v;
    asm("mov.b64 {%0, %1}, %2;" : "=f"(v.x), "=f"(v.y) : "l"(u));
    return v;
}
__device__ __forceinline__ float2 cadd(float2 a, float2 b) {
    unsigned long long r;
    asm("add.rn.f32x2 %0, %1, %2;" : "=l"(r) : "l"(f2u(a)), "l"(f2u(b)));
    return u2f(r);
}
__device__ __forceinline__ float2 csub(float2 a, float2 b) {
    unsigned long long r;
    asm("sub.rn.f32x2 %0, %1, %2;" : "=l"(r) : "l"(f2u(a)), "l"(f2u(b)));
    return u2f(r);
}
__device__ __forceinline__ float2 cmul(float2 a, float2 b) {
    return make_float2(a.x*b.x - a.y*b.y, a.x*b.y + a.y*b.x);
}
template<int S> __device__ __forceinline__ float2 muli(float2 a) {
    return (S > 0) ? make_float2(-a.y, a.x) : make_float2(a.y, -a.x);
}
__device__ __forceinline__ uint32_t s2u(const void* p) {
    uint32_t a;
    asm("{ .reg .u64 t; cvta.to.shared.u64 t, %1; cvt.u32.u64 %0, t; }" : "=r"(a) : "l"(p));
    return a;
}
__device__ __forceinline__ void st_cs_u16(__half* p, __half v) {
    asm volatile("st.global.cs.u16 [%0], %1;" :: "l"(p), "h"(__half_as_ushort(v)));
}

template<int S>
__device__ __forceinline__ void dft8(const float2 v[8], float2 o[8]) {
    const float h = 0.70710678118654752440f;
    float2 e0 = cadd(v[0], v[4]), e1 = csub(v[0], v[4]);
    float2 e2 = cadd(v[2], v[6]), e3 = csub(v[2], v[6]);
    float2 A0 = cadd(e0, e2), A2 = csub(e0, e2);
    float2 ie3 = muli<S>(e3);
    float2 A1 = cadd(e1, ie3), A3 = csub(e1, ie3);
    float2 q0 = cadd(v[1], v[5]), q1 = csub(v[1], v[5]);
    float2 q2 = cadd(v[3], v[7]), q3 = csub(v[3], v[7]);
    float2 B0 = cadd(q0, q2), B2 = csub(q0, q2);
    float2 iq3 = muli<S>(q3);
    float2 B1 = cadd(q1, iq3), B3 = csub(q1, iq3);
    B1 = make_float2(h*(B1.x - S*B1.y), h*(S*B1.x + B1.y));
    B2 = muli<S>(B2);
    B3 = make_float2(h*(-B3.x - S*B3.y), h*(S*B3.x - B3.y));
    o[0] = cadd(A0, B0); o[4] = csub(A0, B0);
    o[1] = cadd(A1, B1); o[5] = csub(A1, B1);
    o[2] = cadd(A2, B2); o[6] = csub(A2, B2);
    o[3] = cadd(A3, B3); o[7] = csub(A3, B3);
}

__device__ __forceinline__ void twchain(float theta, float2 w[8]) {
    float sn, cs; __sincosf(theta, &sn, &cs);
    w[0] = make_float2(1.0f, 0.0f);
    w[1] = make_float2(cs, sn);
    #pragma unroll
    for (int m = 2; m < 8; m++) w[m] = cmul(w[m-1], w[1]);
}

#define FFT_SM 4608   // phys(p) = p + (p>>3)

// fp32 forward radix-8 DIF (fft_x / fft_phi)
__device__ __forceinline__ void fft8_fwd(float2* sm, int t, float2 v[8], float2 o[8]) {
    float2 w[8];
    dft8<-1>(v, o);
    twchain(-TWO_PI * (float)t / 4096.0f, w);
    int b0 = t + (t >> 3);
    sm[b0] = o[0];
    #pragma unroll
    for (int m = 1; m < 8; m++) sm[b0 + 576*m] = cmul(o[m], w[m]);
    __syncthreads();
    int blk = t >> 6, n1 = t & 63;
    int b1 = 576*blk + n1 + (n1 >> 3);
    #pragma unroll
    for (int j = 0; j < 8; j++) v[j] = sm[b1 + 72*j];
    dft8<-1>(v, o);
    twchain(-TWO_PI * (float)n1 / 512.0f, w);
    sm[b1] = o[0];
    #pragma unroll
    for (int m = 1; m < 8; m++) sm[b1 + 72*m] = cmul(o[m], w[m]);
    __syncthreads();
    int sb = t >> 3, n2 = t & 7;
    int b2 = 72*sb + n2;
    #pragma unroll
    for (int j = 0; j < 8; j++) v[j] = sm[b2 + 9*j];
    dft8<-1>(v, o);
    twchain(-TWO_PI * (float)n2 / 64.0f, w);
    sm[b2] = o[0];
    #pragma unroll
    for (int m = 1; m < 8; m++) sm[b2 + 9*m] = cmul(o[m], w[m]);
    __syncthreads();
    int b3 = 9*t;
    #pragma unroll
    for (int j = 0; j < 8; j++) v[j] = sm[b3 + j];
    dft8<-1>(v, o);
}

// Inverse radix-8 DIT with fp16 smem exchanges (compute in fp32).
__device__ __forceinline__ void fft8_inv_h(__half2* sm, int t, float2 v[8], float2 o[8]) {
    float2 w[8];
    dft8<1>(v, o);
    int b3 = 9*t;
    #pragma unroll
    for (int m = 0; m < 8; m++) sm[b3 + m] = __float22half2_rn(o[m]);
    __syncthreads();
    int sb = t >> 3, n2 = t & 7;
    int b2 = 72*sb + n2;
    twchain(TWO_PI * (float)n2 / 64.0f, w);
    #pragma unroll
    for (int m = 0; m < 8; m++) v[m] = cmul(__half22float2(sm[b2 + 9*m]), w[m]);
    dft8<1>(v, o);
    #pragma unroll
    for (int m = 0; m < 8; m++) sm[b2 + 9*m] = __float22half2_rn(o[m]);
    __syncthreads();
    int blk = t >> 6, n1 = t & 63;
    int b1 = 576*blk + n1 + (n1 >> 3);
    twchain(TWO_PI * (float)n1 / 512.0f, w);
    #pragma unroll
    for (int m = 0; m < 8; m++) v[m] = cmul(__half22float2(sm[b1 + 72*m]), w[m]);
    dft8<1>(v, o);
    #pragma unroll
    for (int m = 0; m < 8; m++) sm[b1 + 72*m] = __float22half2_rn(o[m]);
    __syncthreads();
    int b0 = t + (t >> 3);
    twchain(TWO_PI * (float)t / 4096.0f, w);
    #pragma unroll
    for (int m = 0; m < 8; m++) v[m] = cmul(__half22float2(sm[b0 + 576*m]), w[m]);
    dft8<1>(v, o);
}

// ---------------- kernels ----------------

__global__ void transpose_kernel(const float* __restrict__ x) {
    __shared__ float tile[32][33];
    int t0 = blockIdx.x * 32;
    int d0 = blockIdx.y * 32;
    int tx = threadIdx.x, ty = threadIdx.y;
    #pragma unroll
    for (int s = 0; s < 32; s += 8)
        tile[ty + s][tx] = x[(t0 + ty + s) * DDIM + d0 + tx];
    __syncthreads();
    #pragma unroll
    for (int s = 0; s < 32; s += 8)
        g_xT[(size_t)(d0 + ty + s) * LSEQ + t0 + tx] = tile[tx][ty + s];
}

__global__ void __launch_bounds__(512) fft_x_kernel() {
    __shared__ float2 sm[FFT_SM];
    int d = blockIdx.x, t = threadIdx.x;
    float2 v[8], o[8];
    #pragma unroll
    for (int j = 0; j < 4; j++)
        v[j] = make_float2(g_xT[(size_t)d * LSEQ + t + 512*j], 0.0f);
    #pragma unroll
    for (int j = 4; j < 8; j++) v[j] = make_float2(0.0f, 0.0f);
    fft8_fwd(sm, t, v, o);
    float2* dst = g_Xf + (size_t)d * NFFT + t*8;
    #pragma unroll
    for (int m = 0; m < 8; m++) dst[m] = o[m];
}

__global__ void __launch_bounds__(512) fft_phi_kernel(const float* __restrict__ phi) {
    __shared__ float2 sm[FFT_SM];
    int k = blockIdx.x, t = threadIdx.x;
    float2 v[8], o[8];
    #pragma unroll
    for (int j = 0; j < 4; j++)
        v[j] = make_float2(phi[(t + 512*j) * KF + k], 0.0f);
    #pragma unroll
    for (int j = 4; j < 8; j++) v[j] = make_float2(0.0f, 0.0f);
    fft8_fwd(sm, t, v, o);
    const float sc = 1.0f / (float)NFFT;
    float2* dst = g_Vf + (size_t)k * NFFT + t*8;
    #pragma unroll
    for (int m = 0; m < 8; m++) dst[m] = make_float2(o[m].x * sc, o[m].y * sc);
}

// b = d*KF + k: 16 blocks sharing X(d) run concurrently -> L2-hot X.
__global__ void __launch_bounds__(512) conv_ifft_kernel() {
    __shared__ __half2 sm[FFT_SM];
    int b = blockIdx.x;
    int d = b >> 4;
    int k = b & 15;
    int t = threadIdx.x;
    const float4* Xp4 = (const float4*)(g_Xf + (size_t)d * NFFT + t*8);
    const float4* Vp4 = (const float4*)(g_Vf + (size_t)k * NFFT + t*8);
    float2 X[8], V[8], v[8], o[8];
    #pragma unroll
    for (int m = 0; m < 4; m++) {
        float4 xv = Xp4[m];
        X[2*m]   = make_float2(xv.x, xv.y);
        X[2*m+1] = make_float2(xv.z, xv.w);
        float4 vv = Vp4[m];
        V[2*m]   = make_float2(vv.x, vv.y);
        V[2*m+1] = make_float2(vv.z, vv.w);
    }
    #pragma unroll
    for (int c = 0; c < 8; c++) {
        float2 Xs = X[c ^ 4];
        float2 comb = make_float2(X[c].x - Xs.y, X[c].y + Xs.x);  // X + i*Xs
        v[c] = cmul(V[c], comb);
    }
    fft8_inv_h(sm, t, v, o);
    const size_t rowp = (size_t)(k*DDIM + d);
    const size_t rowm = (size_t)(KF*DDIM + k*DDIM + d);
    const float sg = (t & 1) ? -1.0f : 1.0f;
    #pragma unroll
    for (int j = 0; j < 4; j++) {
        int time = t + 512*j;
        st_cs_u16(g_U + rowp * LSEQ + time, __float2half_rn(o[j].x));
        st_cs_u16(g_U + rowm * LSEQ + time, __float2half_rn(o[j].y * sg));
    }
}

// AR rows: g_U[RSPEC + i*DDIM + d][t] = x[t-i][d]
__global__ void arfill_kernel() {
    int idx = blockIdx.x * blockDim.x + threadIdx.x;
    if (idx >= KU * DDIM * (LSEQ/8)) return;
    int tv  = idx & 255;
    int rem = idx >> 8;
    int d   = rem % DDIM;
    int i   = rem / DDIM;
    int t   = tv * 8;
    const float* src = g_xT + (size_t)d * LSEQ;
    __align__(16) __half h[8];
    #pragma unroll
    for (int e = 0; e < 8; e++) {
        int tt = t + e;
        h[e] = __float2half_rn((tt >= i) ? src[tt - i] : 0.0f);
    }
    *(uint4*)(g_U + (size_t)(RSPEC + i*DDIM + d) * LSEQ + t) = *(const uint4*)h;
}

__global__ void mcatT_kernel(const float* __restrict__ Mp,
                             const float* __restrict__ Mm,
                             const float* __restrict__ Mu,
                             const float* __restrict__ sigma) {
    __shared__ float tile[32][33];
    int r0 = blockIdx.x * 32;
    int o0 = blockIdx.y * 32;
    int tx = threadIdx.x, ty = threadIdx.y;
    #pragma unroll
    for (int s = 0; s < 32; s += 8) {
        int r = r0 + ty + s;
        int o = o0 + tx;
        float v;
        if (r < KF*DDIM) {
            v = Mp[(size_t)r * DDIM + o] * sqrtf(sqrtf(sigma[r / DDIM]));
        } else if (r < RSPEC) {
            int rr = r - KF*DDIM;
            v = Mm[(size_t)rr * DDIM + o] * sqrtf(sqrtf(sigma[rr / DDIM]));
        } else {
            v = Mu[(size_t)(r - RSPEC) * DDIM + o];
        }
        tile[ty + s][tx] = v;
    }
    __syncthreads();
    #pragma unroll
    for (int s = 0; s < 32; s += 8)
        g_B[(size_t)(o0 + ty + s) * RTOT + r0 + tx] = __float2half_rn(tile[tx][ty + s]);
}

// ---------------- fp16 mma.sync GEMM, split-K=3, 3-stage single-sync pipeline ----------------
#define BM 128
#define BN 128
#define BK 64
#define KSPLIT 3
#define KLEN (RTOT/KSPLIT)      // 8960
#define NKI (KLEN/BK)           // 140
#define ASTRB 272
#define BSTRB 144
#define ATILEB (BK*ASTRB)       // 17408
#define BTILEB (BN*BSTRB)       // 18432
#define STAGEB (ATILEB + BTILEB)// 35840
#define NSTAGE 3

__device__ __forceinline__ void cp16(uint32_t dst, const void* src) {
    asm volatile("cp.async.cg.shared.global [%0], [%1], 16;" :: "r"(dst), "l"(src));
}
#define LDSM4(R, addr) \
    asm volatile("ldmatrix.sync.aligned.m8n8.x4.shared.b16 {%0,%1,%2,%3}, [%4];" \
        : "=r"((R)[0]), "=r"((R)[1]), "=r"((R)[2]), "=r"((R)[3]) : "r"(addr))
#define LDSM4T(R, addr) \
    asm volatile("ldmatrix.sync.aligned.m8n8.x4.trans.shared.b16 {%0,%1,%2,%3}, [%4];" \
        : "=r"((R)[0]), "=r"((R)[1]), "=r"((R)[2]), "=r"((R)[3]) : "r"(addr))
#define MMA16816(C, A, B) \
    asm volatile("mma.sync.aligned.m16n8k16.row.col.f32.f16.f16.f32 " \
        "{%0,%1,%2,%3}, {%4,%5,%6,%7}, {%8,%9}, {%0,%1,%2,%3};" \
        : "+f"((C)[0]), "+f"((C)[1]), "+f"((C)[2]), "+f"((C)[3]) \
        : "r"((A)[0]), "r"((A)[1]), "r"((A)[2]), "r"((A)[3]), "r"((B)[0]), "r"((B)[1]))

__global__ void __launch_bounds__(256, 2) gemm_kernel() {
    extern __shared__ __align__(16) char dsm[];
    const int tid  = threadIdx.x;
    const int lane = tid & 31;
    const int wid  = tid >> 5;
    const int wm   = wid >> 2;
    const int wn   = wid & 3;
    const int t0   = blockIdx.x * BM;
    const int o0   = blockIdx.y * BN;
    const int ks   = blockIdx.z;
    const size_t koff = (size_t)ks * KLEN;
    const uint32_t sbase = s2u(dsm);

    const __half* pA[4]; uint32_t dA[4];
    const __half* pB[4]; uint32_t dB[4];
    #pragma unroll
    for (int q = 0; q < 4; q++) {
        int ida = tid + q*256;
        int kr = ida >> 4, cc = ida & 15;
        pA[q] = g_U + (koff + kr) * LSEQ + t0 + cc*8;
        dA[q] = (uint32_t)(kr*ASTRB + cc*16);
        int idb = tid + q*256;
        int orow = idb >> 3, bc = idb & 7;
        pB[q] = g_B + (size_t)(o0 + orow) * RTOT + koff + bc*8;
        dB[q] = (uint32_t)(ATILEB + orow*BSTRB + bc*16);
    }

    const int akr = (lane & 7) + ((lane >> 4) << 3);
    const int amc = ((lane >> 3) & 1) * 8;
    const int grp = lane >> 3;
    const int rB = ((grp >> 1) << 3) + (lane & 7);
    const int cB = grp & 1;

    float acc[4][4][4];
    #pragma unroll
    for (int mi = 0; mi < 4; mi++)
        #pragma unroll
        for (int ni = 0; ni < 4; ni++)
            #pragma unroll
            for (int e = 0; e < 4; e++) acc[mi][ni][e] = 0.0f;

    #pragma unroll
    for (int st = 0; st < 2; st++) {
        uint32_t s = sbase + st*STAGEB;
        size_t offA = (size_t)st * BK * LSEQ;
        size_t offB = (size_t)st * BK;
        #pragma unroll
        for (int q = 0; q < 4; q++) {
            cp16(s + dA[q], pA[q] + offA);
            cp16(s + dB[q], pB[q] + offB);
        }
        asm volatile("cp.async.commit_group;");
    }

    int buf = 0;
    #pragma unroll 1
    for (int c = 0; c < NKI; c++) {
        if (c + 1 < NKI) {
            asm volatile("cp.async.wait_group %0;" :: "n"(1));
        } else {
            asm volatile("cp.async.wait_group %0;" :: "n"(0));
        }
        __syncthreads();

        const uint32_t sA = sbase + buf*STAGEB;
        const uint32_t sB = sA + ATILEB;
        #pragma unroll
        for (int j = 0; j < 4; j++) {
            uint32_t a[4][4];
            #pragma unroll
            for (int mi = 0; mi < 4; mi++) {
                uint32_t addr = sA + (uint32_t)((j*16 + akr)*ASTRB + (wm*64 + mi*16 + amc)*2);
                LDSM4T(a[mi], addr);
            }
            uint32_t b[4][2];
            #pragma unroll
            for (int half = 0; half < 2; half++) {
                uint32_t addr = sB + (uint32_t)((wn*32 + half*16 + rB)*BSTRB + (j*16 + cB*8)*2);
                uint32_t r4[4]; LDSM4(r4, addr);
                b[2*half][0]   = r4[0]; b[2*half][1]   = r4[1];
                b[2*half+1][0] = r4[2]; b[2*half+1][1] = r4[3];
            }
            #pragma unroll
            for (int mi = 0; mi < 4; mi++)
                #pragma unroll
                for (int ni = 0; ni < 4; ni++)
                    MMA16816(acc[mi][ni], a[mi], b[ni]);
        }

        if (c + 2 < NKI) {
            int nb = buf + 2; if (nb >= NSTAGE) nb -= NSTAGE;
            uint32_t s = sbase + nb*STAGEB;
            size_t offA = (size_t)(c + 2) * BK * LSEQ;
            size_t offB = (size_t)(c + 2) * BK;
            #pragma unroll
            for (int q = 0; q < 4; q++) {
                cp16(s + dA[q], pA[q] + offA);
                cp16(s + dB[q], pB[q] + offB);
            }
            asm volatile("cp.async.commit_group;");
        }
        buf++; if (buf >= NSTAGE) buf = 0;
    }

    float* pp = g_part + (size_t)ks * LSEQ * DDIM;
    const int row  = lane >> 2;
    const int col2 = (lane & 3) * 2;
    #pragma unroll
    for (int mi = 0; mi < 4; mi++) {
        #pragma unroll
        for (int ni = 0; ni < 4; ni++) {
            int t = t0 + wm*64 + mi*16 + row;
            int o = o0 + wn*32 + ni*8 + col2;
            float* p0 = pp + (size_t)t * DDIM + o;
            float* p1 = pp + (size_t)(t + 8) * DDIM + o;
            p0[0] = acc[mi][ni][0]; p0[1] = acc[mi][ni][1];
            p1[0] = acc[mi][ni][2]; p1[1] = acc[mi][ni][3];
        }
    }
}

__global__ void reduce_kernel(float* __restrict__ out) {
    int i = blockIdx.x * blockDim.x + threadIdx.x;
    const float4* p0 = (const float4*)g_part;
    const float4* p1 = (const float4*)(g_part + (size_t)LSEQ*DDIM);
    const float4* p2 = (const float4*)(g_part + 2*(size_t)LSEQ*DDIM);
    float4 a = p0[i], b = p1[i], c = p2[i];
    ((float4*)out)[i] = make_float4(a.x+b.x+c.x, a.y+b.y+c.y, a.z+b.z+c.z, a.w+b.w+c.w);
}

// ---------------- launch ----------------
extern "C" void kernel_launch(void* const* d_in, const int* in_sizes, int n_in,
                              void* d_out, int out_size) {
    const float* x     = (const float*)d_in[0];
    const float* phi   = (const float*)d_in[1];
    const float* sigma = (const float*)d_in[2];
    const float* Mp    = (const float*)d_in[3];
    const float* Mm    = (const float*)d_in[4];
    const float* Mu    = (const float*)d_in[5];
    float* out = (float*)d_out;

    cudaFuncSetAttribute(gemm_kernel, cudaFuncAttributeMaxDynamicSharedMemorySize, NSTAGE*STAGEB);

    transpose_kernel<<<dim3(LSEQ/32, DDIM/32), dim3(32, 8)>>>(x);
    fft_x_kernel<<<DDIM, 512>>>();
    fft_phi_kernel<<<KF, 512>>>(phi);
    conv_ifft_kernel<<<KF*DDIM, 512>>>();
    arfill_kernel<<<(KU*DDIM*(LSEQ/8) + 255)/256, 256>>>();
    mcatT_kernel<<<dim3(RTOT/32, DDIM/32), dim3(32, 8)>>>(Mp, Mm, Mu, sigma);
    gemm_kernel<<<dim3(LSEQ/BM, DDIM/BN, KSPLIT), 256, NSTAGE*STAGEB>>>();
    reduce_kernel<<<(LSEQ*DDIM/4 + 255)/256, 256>>>(out);
}